// round 16
// baseline (speedup 1.0000x reference)
#include <cuda_runtime.h>
#include <cuda_bf16.h>
#include <math.h>
#include <stdint.h>

#define DD   128
#define NBR  30
#define NQ   4096
#define FEWN 5
#define H2   256
#define H4   512
#define NG   2048
#define RQ   (NQ*NBR)
#define RS   (FEWN*NBR)
#define R_TOT (2*RQ + 2*RS)
#define MB   (2*NQ)

// ---------------- scratch ----------------
__device__ float g_logits[2*R_TOT];
__device__ float g_query[MB*H2];
__device__ float g_support[2*FEWN*H2];
__device__ float g_qg[MB*H2];
__device__ float g_sg[2*FEWN*H2];
__device__ float g_h1[(size_t)MB*H4];
__device__ float g_z[MB*H2];
__device__ float g_sh1[2*FEWN*H4];
__device__ float g_sz[2*FEWN*H2];
__device__ float g_Gx[(size_t)MB*NG];      // gate-permuted layout: col = 4u+gate
__device__ float g_SW[2*FEWN*NG];          // gate-permuted columns
__device__ float g_smean[2*H2];
__device__ float g_c[(size_t)MB*H4];
__device__ float g_hA[MB*H2];              // ping-pong h buffers
__device__ float g_hB[MB*H2];
__device__ float g_attn[MB*FEWN];
__device__ float g_bsum[NG];               // gate-permuted

__device__ __forceinline__ float sigm(float x) { return 1.f/(1.f+expf(-x)); }

__device__ __forceinline__ uint32_t smem_u32(const void* p) {
    uint32_t a;
    asm("{ .reg .u64 t; cvta.to.shared.u64 t, %1; cvt.u32.u64 %0, t; }" : "=r"(a) : "l"(p));
    return a;
}

// permuted gate index: n = 4u+g  ->  original row = g*512 + u
__device__ __forceinline__ int gperm(int n) { return ((n & 3) << 9) + (n >> 2); }

// ---------------- bf16 mma helpers ----------------
__device__ __forceinline__ void mma_bf16(float* c, const uint32_t* a, const uint32_t* b) {
    asm volatile("mma.sync.aligned.m16n8k16.row.col.f32.bf16.bf16.f32 "
        "{%0,%1,%2,%3}, {%4,%5,%6,%7}, {%8,%9}, {%0,%1,%2,%3};"
        : "+f"(c[0]), "+f"(c[1]), "+f"(c[2]), "+f"(c[3])
        : "r"(a[0]), "r"(a[1]), "r"(a[2]), "r"(a[3]), "r"(b[0]), "r"(b[1]));
}
__device__ __forceinline__ void ldm_x4(uint32_t* r, uint32_t addr) {
    asm volatile("ldmatrix.sync.aligned.m8n8.x4.shared.b16 {%0,%1,%2,%3}, [%4];"
        : "=r"(r[0]), "=r"(r[1]), "=r"(r[2]), "=r"(r[3]) : "r"(addr));
}
__device__ __forceinline__ void ldm_x2(uint32_t* r, uint32_t addr) {
    asm volatile("ldmatrix.sync.aligned.m8n8.x2.shared.b16 {%0,%1}, [%2];"
        : "=r"(r[0]), "=r"(r[1]) : "r"(addr));
}

// convert float4 -> hi/lo bf16 quads, store to smem (8-byte stores)
__device__ __forceinline__ void cvt_store(float4 v, uint16_t* hb, uint16_t* lb, int idx) {
    __nv_bfloat16 h0 = __float2bfloat16(v.x), h1 = __float2bfloat16(v.y);
    __nv_bfloat16 h2 = __float2bfloat16(v.z), h3 = __float2bfloat16(v.w);
    uint32_t p0 = ((uint32_t)__bfloat16_as_ushort(h1) << 16) | __bfloat16_as_ushort(h0);
    uint32_t p1 = ((uint32_t)__bfloat16_as_ushort(h3) << 16) | __bfloat16_as_ushort(h2);
    *(uint2*)(hb + idx) = make_uint2(p0, p1);
    __nv_bfloat16 l0 = __float2bfloat16(v.x - __bfloat162float(h0));
    __nv_bfloat16 l1 = __float2bfloat16(v.y - __bfloat162float(h1));
    __nv_bfloat16 l2 = __float2bfloat16(v.z - __bfloat162float(h2));
    __nv_bfloat16 l3 = __float2bfloat16(v.w - __bfloat162float(h3));
    uint32_t q0 = ((uint32_t)__bfloat16_as_ushort(l1) << 16) | __bfloat16_as_ushort(l0);
    uint32_t q1 = ((uint32_t)__bfloat16_as_ushort(l3) << 16) | __bfloat16_as_ushort(l2);
    *(uint2*)(lb + idx) = make_uint2(q0, q1);
}

#define ASTR 40     // bf16 elems per smem row (32 data + 8 pad; conflict-free ldmatrix)

// ---- shared GEMM mainloop body ----
#define GEMM_MAINLOOP_STEP()                                                     \
    _Pragma("unroll")                                                            \
    for (int ks = 0; ks < 2; ks++) {                                             \
        const uint32_t kso = (uint32_t)(ks * 16) * 2;                            \
        uint32_t bh[4][2], bl[4][2];                                             \
        _Pragma("unroll")                                                        \
        for (int nt = 0; nt < 4; nt++) {                                         \
            uint32_t ad = boff + kso + (uint32_t)(nt * 8 * ASTR) * 2;            \
            ldm_x2(bh[nt], bbh + ad);                                            \
            ldm_x2(bl[nt], bbl + ad);                                            \
        }                                                                        \
        _Pragma("unroll")                                                        \
        for (int mt = 0; mt < 4; mt++) {                                         \
            uint32_t ad = aoff + kso + (uint32_t)(mt * 16 * ASTR) * 2;           \
            uint32_t ah[4], al[4];                                               \
            ldm_x4(ah, abh + ad);                                                \
            ldm_x4(al, abl + ad);                                                \
            _Pragma("unroll")                                                    \
            for (int nt = 0; nt < 4; nt++) {                                     \
                mma_bf16(acc[mt][nt], ah, bh[nt]);                               \
                mma_bf16(acc[mt][nt], ah, bl[nt]);                               \
                mma_bf16(acc[mt][nt], al, bh[nt]);                               \
            }                                                                    \
        }                                                                        \
    }

// ============ bf16x2 TN GEMM (R8 style): C = A[M,K] @ W[N,K]^T ============
__global__ __launch_bounds__(256, 2) void tgemm(
    int M, int N, int K,
    const float* __restrict__ A, int lda,
    const float* __restrict__ W, int ldw,
    const float* __restrict__ bias,
    float* __restrict__ C, int ldc,
    int epi, const float* __restrict__ res, int ldres)
{
    __shared__ uint16_t Ah[128*ASTR], Al[128*ASTR], Bh[128*ASTR], Bl[128*ASTR];
    const int tid = threadIdx.x, lane = tid & 31, wid = tid >> 5;
    const int wm = wid >> 2, wn = wid & 3;
    const int bm = blockIdx.x * 128, bn = blockIdx.y * 128;

    float acc[4][4][4];
    #pragma unroll
    for (int i = 0; i < 4; i++)
        #pragma unroll
        for (int j = 0; j < 4; j++)
            #pragma unroll
            for (int l = 0; l < 4; l++) acc[i][j][l] = 0.f;

    const uint32_t abh = smem_u32(Ah), abl = smem_u32(Al);
    const uint32_t bbh = smem_u32(Bh), bbl = smem_u32(Bl);
    const int m_off = wm*64 + (lane & 7) + ((lane >> 3) & 1) * 8;
    const int ka    = (lane >> 4) * 8;
    const uint32_t aoff = (uint32_t)(m_off * ASTR + ka) * 2;
    const int n_off = wn*32 + (lane & 7);
    const int kb    = ((lane >> 3) & 1) * 8;
    const uint32_t boff = (uint32_t)(n_off * ASTR + kb) * 2;

    const int nkt = K >> 5;
    for (int kt = 0; kt < nkt; kt++) {
        const int k0 = kt << 5;
        #pragma unroll
        for (int l = 0; l < 4; l++) {
            int j = tid + l*256;
            int row = j >> 3, c4 = (j & 7) << 2;
            float4 va = *(const float4*)(A + (size_t)(bm + row)*lda + k0 + c4);
            cvt_store(va, Ah, Al, row*ASTR + c4);
            float4 vb = *(const float4*)(W + (size_t)(bn + row)*ldw + k0 + c4);
            cvt_store(vb, Bh, Bl, row*ASTR + c4);
        }
        __syncthreads();
        GEMM_MAINLOOP_STEP();
        __syncthreads();
    }
    #pragma unroll
    for (int mt = 0; mt < 4; mt++) {
        int rlo = bm + wm*64 + mt*16 + (lane >> 2);
        #pragma unroll
        for (int nt = 0; nt < 4; nt++) {
            int col = bn + wn*32 + nt*8 + ((lane & 3) << 1);
            #pragma unroll
            for (int hf = 0; hf < 2; hf++) {
                int row = rlo + hf*8;
                float2 v = make_float2(acc[mt][nt][hf*2], acc[mt][nt][hf*2+1]);
                if (bias) { v.x += bias[col]; v.y += bias[col+1]; }
                if (epi == 1) { v.x = fmaxf(v.x, 0.f); v.y = fmaxf(v.y, 0.f); }
                else if (epi == 2) {
                    float2 rv = *(const float2*)(res + (size_t)row*ldres + col);
                    v.x += rv.x; v.y += rv.y;
                }
                *(float2*)(C + (size_t)row*ldc + col) = v;
            }
        }
    }
}

// ============ GEMM + fused LSTM cell epilogue (gate-permuted N) ============
// t==0: A=qg, W=Wih (ldw=H2); gates = acc + bsum; store Gx; cprev=0
// t>0 : A=h_in, W=Whh (ldw=H4); gates = acc + Gx + attn@SW
// epilogue operands (SW slice, attn rows, bsum slice) staged in smem at start.
__global__ __launch_bounds__(256, 2) void tgemm_lstm(
    int t, const float* __restrict__ A,
    const float* __restrict__ W, int ldw,
    float* __restrict__ hout)
{
    __shared__ uint16_t Ah[128*ASTR], Al[128*ASTR], Bh[128*ASTR], Bl[128*ASTR];
    __shared__ float sSW[FEWN][128];     // SW[f][bn..bn+127] (t>0)
    __shared__ float sAttnF[128*FEWN];   // attn rows bm..bm+127 (t>0)
    __shared__ float sAux[128];          // bsum[bn..bn+127] (t==0)
    const int tid = threadIdx.x, lane = tid & 31, wid = tid >> 5;
    const int wm = wid >> 2, wn = wid & 3;
    const int bm = blockIdx.x * 128, bn = blockIdx.y * 128;
    const int path = bm >> 12;

    // ---- stage epilogue operands (launch-invariant; covered by mainloop sync) ----
    if (t == 0) {
        if (tid < 128) sAux[tid] = g_bsum[bn + tid];
    } else {
        if (tid < 128) {
            #pragma unroll
            for (int f = 0; f < FEWN; f++)
                sSW[f][tid] = g_SW[(size_t)path*FEWN*NG + f*NG + bn + tid];
        }
        for (int i = tid; i < 128*FEWN; i += 256)
            sAttnF[i] = g_attn[(size_t)bm*FEWN + i];
    }

    float acc[4][4][4];
    #pragma unroll
    for (int i = 0; i < 4; i++)
        #pragma unroll
        for (int j = 0; j < 4; j++)
            #pragma unroll
            for (int l = 0; l < 4; l++) acc[i][j][l] = 0.f;

    const uint32_t abh = smem_u32(Ah), abl = smem_u32(Al);
    const uint32_t bbh = smem_u32(Bh), bbl = smem_u32(Bl);
    const int m_off = wm*64 + (lane & 7) + ((lane >> 3) & 1) * 8;
    const int ka    = (lane >> 4) * 8;
    const uint32_t aoff = (uint32_t)(m_off * ASTR + ka) * 2;
    const int n_off = wn*32 + (lane & 7);
    const int kb    = ((lane >> 3) & 1) * 8;
    const uint32_t boff = (uint32_t)(n_off * ASTR + kb) * 2;

    for (int kt = 0; kt < 8; kt++) {       // K = 256
        const int k0 = kt << 5;
        #pragma unroll
        for (int l = 0; l < 4; l++) {
            int j = tid + l*256;
            int row = j >> 3, c4 = (j & 7) << 2;
            float4 va = *(const float4*)(A + (size_t)(bm + row)*H2 + k0 + c4);
            cvt_store(va, Ah, Al, row*ASTR + c4);
            int wr = gperm(bn + row);
            float4 vb = *(const float4*)(W + (size_t)wr*ldw + k0 + c4);
            cvt_store(vb, Bh, Bl, row*ASTR + c4);
        }
        __syncthreads();
        GEMM_MAINLOOP_STEP();
        __syncthreads();
    }
    // fused LSTM epilogue (smem-staged operands)
    const int sub = (lane & 3);
    const bool isIF = ((sub & 1) == 0);          // cols%4 in {0,1}=(i,f); {2,3}=(g,o)
    #pragma unroll
    for (int mt = 0; mt < 4; mt++) {
        #pragma unroll
        for (int hf = 0; hf < 2; hf++) {
            int rl = wm*64 + mt*16 + (lane >> 2) + hf*8;   // local row
            int row = bm + rl;
            float att[FEWN];
            if (t > 0) {
                #pragma unroll
                for (int f = 0; f < FEWN; f++) att[f] = sAttnF[rl*FEWN + f];
            }
            #pragma unroll
            for (int nt = 0; nt < 4; nt++) {
                int cl = wn*32 + nt*8 + (sub << 1);        // local col
                int col = bn + cl;
                float2 v = make_float2(acc[mt][nt][hf*2], acc[mt][nt][hf*2+1]);
                if (t == 0) {
                    v.x += sAux[cl]; v.y += sAux[cl+1];
                    *(float2*)(g_Gx + (size_t)row*NG + col) = v;
                } else {
                    float2 gx = *(const float2*)(g_Gx + (size_t)row*NG + col);
                    v.x += gx.x; v.y += gx.y;
                    #pragma unroll
                    for (int f = 0; f < FEWN; f++) {
                        v.x += att[f]*sSW[f][cl];
                        v.y += att[f]*sSW[f][cl+1];
                    }
                }
                int u = col >> 2;
                // even lane: v=(i,f). odd lane: v=(g,o). exchange g, then cn.
                float gOther = __shfl_xor_sync(~0u, v.x, 1);
                float cn = 0.f;
                if (isIF) {
                    float cprev = (t > 0) ? g_c[(size_t)row*H4 + u] : 0.f;
                    cn = sigm(v.y)*cprev + sigm(v.x)*tanhf(gOther);
                    g_c[(size_t)row*H4 + u] = cn;
                }
                float cnX = __shfl_xor_sync(~0u, cn, 1);
                if (!isIF && u < H2) {
                    hout[(size_t)row*H2 + u] = g_qg[(size_t)row*H2 + u] + sigm(v.y)*tanhf(cnX);
                }
            }
        }
    }
}

// ============ neighbor logits: gathered bf16x2 GEMM + tanh/dot epilogue ============
__global__ __launch_bounds__(256, 2) void neigh_tc(
    const float* __restrict__ emb, const float* __restrict__ embv,
    const float* __restrict__ nW,  const float* __restrict__ nWb,
    const float* __restrict__ nu,  const float* __restrict__ nub,
    const float* __restrict__ nvW, const float* __restrict__ nvWb,
    const float* __restrict__ nvu, const float* __restrict__ nvub,
    const int* __restrict__ ql, const int* __restrict__ qr,
    const int* __restrict__ sl, const int* __restrict__ sr)
{
    __shared__ uint16_t Ah[128*ASTR], Al[128*ASTR], Bh[128*ASTR], Bl[128*ASTR];
    __shared__ int relS[128], entS[128];
    __shared__ float sU[128], sB[128];
    __shared__ float sred[4][128];

    const int path = blockIdx.y;
    const float* tab = path ? embv : emb;
    const float* Wt  = path ? nvW  : nW;
    const float* Wb  = path ? nvWb : nWb;
    const float* uu  = path ? nvu  : nu;
    const float  ub  = path ? nvub[0] : nub[0];

    const int tid = threadIdx.x, lane = tid & 31, wid = tid >> 5;
    const int wm = wid >> 2, wn = wid & 3;
    const int bm = blockIdx.x * 128;

    if (tid < 128) {
        int r = bm + tid;
        int rel = 0, ent = 0;
        if (r < R_TOT) {
            const int* conn; int local;
            if (r < RQ)            { conn = ql; local = r; }
            else if (r < 2*RQ)     { conn = qr; local = r - RQ; }
            else if (r < 2*RQ+RS)  { conn = sl; local = r - 2*RQ; }
            else                   { conn = sr; local = r - 2*RQ - RS; }
            rel = conn[local*2]; ent = conn[local*2+1];
        }
        relS[tid] = rel; entS[tid] = ent;
        sU[tid] = uu[tid]; sB[tid] = Wb[tid];
    }
    __syncthreads();

    float acc[4][4][4];
    #pragma unroll
    for (int i = 0; i < 4; i++)
        #pragma unroll
        for (int j = 0; j < 4; j++)
            #pragma unroll
            for (int l = 0; l < 4; l++) acc[i][j][l] = 0.f;

    const uint32_t abh = smem_u32(Ah), abl = smem_u32(Al);
    const uint32_t bbh = smem_u32(Bh), bbl = smem_u32(Bl);
    const int m_off = wm*64 + (lane & 7) + ((lane >> 3) & 1) * 8;
    const int ka    = (lane >> 4) * 8;
    const uint32_t aoff = (uint32_t)(m_off * ASTR + ka) * 2;
    const int n_off = wn*32 + (lane & 7);
    const int kb    = ((lane >> 3) & 1) * 8;
    const uint32_t boff = (uint32_t)(n_off * ASTR + kb) * 2;

    for (int kt = 0; kt < 8; kt++) {               // K = 256
        const int half = kt >> 2;
        const int koff = (kt & 3) << 5;
        #pragma unroll
        for (int l = 0; l < 4; l++) {
            int j = tid + l*256;
            int row = j >> 3, c4 = (j & 7) << 2;
            int sym = half ? entS[row] : relS[row];
            float4 va = *(const float4*)(tab + (size_t)sym*DD + koff + c4);
            cvt_store(va, Ah, Al, row*ASTR + c4);
            float4 vb = *(const float4*)(Wt + (size_t)row*(2*DD) + (kt << 5) + c4);
            cvt_store(vb, Bh, Bl, row*ASTR + c4);
        }
        __syncthreads();
        GEMM_MAINLOOP_STEP();
        __syncthreads();
    }
    #pragma unroll
    for (int mt = 0; mt < 4; mt++) {
        float pLo = 0.f, pHi = 0.f;
        #pragma unroll
        for (int nt = 0; nt < 4; nt++) {
            int c0 = wn*32 + nt*8 + ((lane & 3) << 1);
            pLo += sU[c0]   * tanhf(acc[mt][nt][0] + sB[c0]);
            pLo += sU[c0+1] * tanhf(acc[mt][nt][1] + sB[c0+1]);
            pHi += sU[c0]   * tanhf(acc[mt][nt][2] + sB[c0]);
            pHi += sU[c0+1] * tanhf(acc[mt][nt][3] + sB[c0+1]);
        }
        pLo += __shfl_xor_sync(~0u, pLo, 1); pLo += __shfl_xor_sync(~0u, pLo, 2);
        pHi += __shfl_xor_sync(~0u, pHi, 1); pHi += __shfl_xor_sync(~0u, pHi, 2);
        if ((lane & 3) == 0) {
            int rl = wm*64 + mt*16 + (lane >> 2);
            sred[wn][rl]   = pLo;
            sred[wn][rl+8] = pHi;
        }
    }
    __syncthreads();
    if (tid < 128) {
        int row = bm + tid;
        if (row < R_TOT) {
            float s = sred[0][tid] + sred[1][tid] + sred[2][tid] + sred[3][tid];
            g_logits[(size_t)path*R_TOT + row] = s + ub;
        }
    }
}

// ---------------- small GEMM (warp per output; optional gate-perm on W rows) ----
__global__ __launch_bounds__(256) void small_gemm(
    int M, int N, int K,
    const float* __restrict__ A, int lda,
    const float* __restrict__ W, int ldw,
    const float* __restrict__ bias,
    float* __restrict__ C, int ldc,
    int epi, const float* __restrict__ res, int ldres, int perm)
{
    int w = (blockIdx.x * 256 + threadIdx.x) >> 5;
    int lane = threadIdx.x & 31;
    if (w >= M * N) return;
    int m = w / N, n = w % N;
    int wr = perm ? gperm(n) : n;
    float p = 0.f;
    for (int k = lane; k < K; k += 32) p += A[(size_t)m*lda + k] * W[(size_t)wr*ldw + k];
    #pragma unroll
    for (int o = 16; o; o >>= 1) p += __shfl_xor_sync(~0u, p, o);
    if (lane == 0) {
        if (bias) p += bias[n];
        if (epi == 1) p = fmaxf(p, 0.f);
        else if (epi == 2) p += res[(size_t)m*ldres + n];
        C[(size_t)m*ldc + n] = p;
    }
}

// ---------------- softmax over 30 neighbors + weighted pool + tanh --------------
__global__ __launch_bounds__(128) void pool_kernel(
    const float* __restrict__ emb,
    const int* __restrict__ ql, const int* __restrict__ qr,
    const int* __restrict__ sl, const int* __restrict__ sr)
{
    const int gs = blockIdx.x;
    const int tid = threadIdx.x;
    __shared__ float att[2][NBR];
    __shared__ int entS[NBR];
    int set, local;
    if (gs < NQ)            { set=0; local=gs; }
    else if (gs < 2*NQ)     { set=1; local=gs-NQ; }
    else if (gs < 2*NQ+FEWN){ set=2; local=gs-2*NQ; }
    else                    { set=3; local=gs-2*NQ-FEWN; }
    const int rowbase = (set==0?0: set==1?RQ : set==2?2*RQ : 2*RQ+RS) + local*NBR;
    const int* conn = set==0?ql : set==1?qr : set==2?sl : sr;
    const int warp = tid >> 5, lane = tid & 31;

    if (warp == 0 && lane < NBR) entS[lane] = conn[(local*NBR+lane)*2+1];
    if (warp < 2) {
        float v = (lane < NBR) ? g_logits[(size_t)warp*R_TOT + rowbase + lane] : -1e30f;
        float m = v;
        #pragma unroll
        for (int o = 16; o; o >>= 1) m = fmaxf(m, __shfl_xor_sync(~0u, m, o));
        float e = (lane < NBR) ? expf(v - m) : 0.f;
        float s = e;
        #pragma unroll
        for (int o = 16; o; o >>= 1) s += __shfl_xor_sync(~0u, s, o);
        if (lane < NBR) att[warp][lane] = e / s;
    }
    __syncthreads();
    const int d = tid;
    float a0 = 0.f, a1 = 0.f;
    #pragma unroll 6
    for (int nb = 0; nb < NBR; nb++) {
        float ev = emb[(size_t)entS[nb]*DD + d];
        a0 += att[0][nb]*ev;
        a1 += att[1][nb]*ev;
    }
    float t0 = tanhf(a0), t1 = tanhf(a1);
    if (set < 2) {
        g_query[((size_t)0*NQ + local)*H2 + set*DD + d] = t0;
        g_query[((size_t)NQ + local)*H2 + set*DD + d]   = t1;
    } else {
        int s2 = set - 2;
        g_support[(0*FEWN + local)*H2 + s2*DD + d] = t0;
        g_support[(1*FEWN + local)*H2 + s2*DD + d] = t1;
    }
}

// ---------------- layernorm (ddof=1, eps added to sigma) ------------------------
__global__ __launch_bounds__(256) void ln_kernel(
    const float* __restrict__ Z, float* __restrict__ O,
    const float* __restrict__ ga, const float* __restrict__ gb)
{
    const int row = blockIdx.x, c = threadIdx.x;
    float z = Z[(size_t)row*H2 + c];
    __shared__ float s1[H2], s2[H2];
    s1[c] = z; s2[c] = z*z;
    __syncthreads();
    for (int o = 128; o; o >>= 1) {
        if (c < o) { s1[c] += s1[c+o]; s2[c] += s2[c+o]; }
        __syncthreads();
    }
    float mu  = s1[0] * (1.f/H2);
    float var = (s2[0] - (float)H2*mu*mu) * (1.f/(H2-1));
    float sig = sqrtf(fmaxf(var, 0.f));
    O[(size_t)row*H2 + c] = (z - mu)/(sig + 1e-3f)*ga[c] + gb[c];
}

__global__ void smean_kernel() {
    int p = blockIdx.x, c = threadIdx.x;
    float s = 0.f;
    #pragma unroll
    for (int f = 0; f < FEWN; f++) s += g_sg[(p*FEWN + f)*H2 + c];
    g_smean[p*H2 + c] = s * (1.f/FEWN);
}

__global__ void bsum_kernel(const float* __restrict__ bih, const float* __restrict__ bhh) {
    int i = blockIdx.x*blockDim.x + threadIdx.x;
    if (i < NG) { int o = gperm(i); g_bsum[i] = bih[o] + bhh[o]; }
}

// ---------------- attention over 5 support rows ---------------------------------
__global__ __launch_bounds__(128) void attn_kernel(const float* __restrict__ h)
{
    int r = blockIdx.x*4 + (threadIdx.x >> 5);
    int lane = threadIdx.x & 31;
    const float* sg = g_sg + (size_t)(r >> 12) * FEWN * H2;
    float sc[FEWN];
    #pragma unroll
    for (int f = 0; f < FEWN; f++) {
        float p = 0.f;
        for (int c = lane; c < H2; c += 32) p += h[(size_t)r*H2 + c]*sg[f*H2 + c];
        #pragma unroll
        for (int o = 16; o; o >>= 1) p += __shfl_xor_sync(~0u, p, o);
        sc[f] = p;
    }
    float m = sc[0];
    #pragma unroll
    for (int f = 1; f < FEWN; f++) m = fmaxf(m, sc[f]);
    float e[FEWN], s = 0.f;
    #pragma unroll
    for (int f = 0; f < FEWN; f++) { e[f] = expf(sc[f]-m); s += e[f]; }
    if (lane < FEWN) g_attn[r*FEWN + lane] = e[lane]/s;
}

__global__ __launch_bounds__(128) void score_kernel(const float* __restrict__ h,
                                                    float* __restrict__ out)
{
    int r = blockIdx.x*4 + (threadIdx.x >> 5);
    int lane = threadIdx.x & 31;
    const float* sm = g_smean + (size_t)(r >> 12) * H2;
    float p = 0.f;
    for (int c = lane; c < H2; c += 32) p += h[(size_t)r*H2 + c]*sm[c];
    #pragma unroll
    for (int o = 16; o; o >>= 1) p += __shfl_xor_sync(~0u, p, o);
    if (lane == 0) out[r] = p;
}

// ---------------- host orchestration --------------------------------------------
extern "C" void kernel_launch(void* const* d_in, const int* in_sizes, int n_in,
                              void* d_out, int out_size)
{
    (void)in_sizes; (void)n_in; (void)out_size;
    const float* emb   = (const float*)d_in[0];
    const float* embv  = (const float*)d_in[1];
    const float* nW    = (const float*)d_in[2];
    const float* nWb   = (const float*)d_in[3];
    const float* nu    = (const float*)d_in[4];
    const float* nub   = (const float*)d_in[5];
    const float* nvW   = (const float*)d_in[6];
    const float* nvWb  = (const float*)d_in[7];
    const float* nvu   = (const float*)d_in[8];
    const float* nvub  = (const float*)d_in[9];
    const float* p1W   = (const float*)d_in[10];
    const float* p1b   = (const float*)d_in[11];
    const float* p2W   = (const float*)d_in[12];
    const float* p2b   = (const float*)d_in[13];
    const float* ln_a  = (const float*)d_in[14];
    const float* ln_b  = (const float*)d_in[15];
    const float* Wih   = (const float*)d_in[16];
    const float* Whh   = (const float*)d_in[17];
    const float* bih   = (const float*)d_in[18];
    const float* bhh   = (const float*)d_in[19];
    const int* ql = (const int*)d_in[20];
    const int* qr = (const int*)d_in[21];
    const int* sl = (const int*)d_in[22];
    const int* sr = (const int*)d_in[23];
    float* out = (float*)d_out;

    float *p_query, *p_support, *p_qg, *p_sg, *p_h1, *p_z, *p_sh1, *p_sz,
          *p_SW, *p_hA, *p_hB;
    cudaGetSymbolAddress((void**)&p_query,   g_query);
    cudaGetSymbolAddress((void**)&p_support, g_support);
    cudaGetSymbolAddress((void**)&p_qg,      g_qg);
    cudaGetSymbolAddress((void**)&p_sg,      g_sg);
    cudaGetSymbolAddress((void**)&p_h1,      g_h1);
    cudaGetSymbolAddress((void**)&p_z,       g_z);
    cudaGetSymbolAddress((void**)&p_sh1,     g_sh1);
    cudaGetSymbolAddress((void**)&p_sz,      g_sz);
    cudaGetSymbolAddress((void**)&p_SW,      g_SW);
    cudaGetSymbolAddress((void**)&p_hA,      g_hA);
    cudaGetSymbolAddress((void**)&p_hB,      g_hB);

    bsum_kernel<<<(NG+255)/256, 256>>>(bih, bhh);

    dim3 gN((R_TOT + 127)/128, 2);
    neigh_tc<<<gN, 256>>>(emb, embv, nW, nWb, nu, nub,
                          nvW, nvWb, nvu, nvub, ql, qr, sl, sr);
    pool_kernel<<<2*NQ + 2*FEWN, 128>>>(emb, ql, qr, sl, sr);

    // ---- support rows (M=10, both paths) ----
    {
        int M = 2*FEWN;
        small_gemm<<<(M*H4*32 + 255)/256, 256>>>(M, H4, H2, p_support, H2, p1W, H2,
                                                 p1b, p_sh1, H4, 1, nullptr, 0, 0);
        small_gemm<<<(M*H2*32 + 255)/256, 256>>>(M, H2, H4, p_sh1, H4, p2W, H4,
                                                 p2b, p_sz, H2, 2, p_support, H2, 0);
        ln_kernel<<<M, 256>>>(p_sz, p_sg, ln_a, ln_b);
        // SW in gate-permuted columns: weight row = gperm(n), cols 256..511 of Whh
        small_gemm<<<(M*NG*32 + 255)/256, 256>>>(M, NG, H2, p_sg, H2, Whh + 256, H4,
                                                 nullptr, p_SW, NG, 0, nullptr, 0, 1);
        smean_kernel<<<2, 256>>>();
    }

    // ---- support encoder on queries (M=8192) ----
    tgemm<<<dim3(MB/128, H4/128), 256>>>(MB, H4, H2, p_query, H2, p1W, H2,
                                         p1b, p_h1, H4, 1, nullptr, 0);
    tgemm<<<dim3(MB/128, H2/128), 256>>>(MB, H2, H4, p_h1, H4, p2W, H4,
                                         p2b, p_z, H2, 2, p_query, H2);
    ln_kernel<<<MB, 256>>>(p_z, p_qg, ln_a, ln_b);

    // ---- LSTM: GEMM with fused cell epilogue (gate-permuted, ping-pong h) ----
    tgemm_lstm<<<dim3(MB/128, NG/128), 256>>>(0, p_qg, Wih, H2, p_hA);
    attn_kernel<<<MB/4, 128>>>(p_hA);
    tgemm_lstm<<<dim3(MB/128, NG/128), 256>>>(1, p_hA, Whh, H4, p_hB);
    attn_kernel<<<MB/4, 128>>>(p_hB);
    tgemm_lstm<<<dim3(MB/128, NG/128), 256>>>(2, p_hB, Whh, H4, p_hA);
    attn_kernel<<<MB/4, 128>>>(p_hA);
    tgemm_lstm<<<dim3(MB/128, NG/128), 256>>>(3, p_hA, Whh, H4, p_hB);
    score_kernel<<<MB/4, 128>>>(p_hB, out);
}

// round 17
// speedup vs baseline: 1.3835x; 1.3835x over previous
#include <cuda_runtime.h>
#include <cuda_fp16.h>
#include <math.h>
#include <stdint.h>

#define DD   128
#define NBR  30
#define NQ   4096
#define FEWN 5
#define H2   256
#define H4   512
#define NG   2048
#define RQ   (NQ*NBR)
#define RS   (FEWN*NBR)
#define R_TOT (2*RQ + 2*RS)
#define MB   (2*NQ)

// ---------------- scratch ----------------
__device__ float g_logits[2*R_TOT];
__device__ float g_query[MB*H2];
__device__ float g_support[2*FEWN*H2];
__device__ float g_qg[MB*H2];
__device__ float g_sg[2*FEWN*H2];
__device__ float g_h1[(size_t)MB*H4];
__device__ float g_z[MB*H2];
__device__ float g_sh1[2*FEWN*H4];
__device__ float g_sz[2*FEWN*H2];
__device__ float g_Gx[(size_t)MB*NG];
__device__ float g_Ds[(size_t)MB*NG];
__device__ float g_SW[2*FEWN*NG];
__device__ float g_smean[2*H2];
__device__ float g_c[(size_t)MB*H4];
__device__ float g_h[MB*H2];
__device__ float g_attn[MB*FEWN];
__device__ float g_bsum[NG];

__device__ __forceinline__ float sigm(float x) { return 1.f/(1.f+expf(-x)); }

__device__ __forceinline__ uint32_t smem_u32(const void* p) {
    uint32_t a;
    asm("{ .reg .u64 t; cvta.to.shared.u64 t, %1; cvt.u32.u64 %0, t; }" : "=r"(a) : "l"(p));
    return a;
}

// ---------------- fp16 mma helpers ----------------
__device__ __forceinline__ void mma_f16(float* c, const uint32_t* a, const uint32_t* b) {
    asm volatile("mma.sync.aligned.m16n8k16.row.col.f32.f16.f16.f32 "
        "{%0,%1,%2,%3}, {%4,%5,%6,%7}, {%8,%9}, {%0,%1,%2,%3};"
        : "+f"(c[0]), "+f"(c[1]), "+f"(c[2]), "+f"(c[3])
        : "r"(a[0]), "r"(a[1]), "r"(a[2]), "r"(a[3]), "r"(b[0]), "r"(b[1]));
}
__device__ __forceinline__ void ldm_x4(uint32_t* r, uint32_t addr) {
    asm volatile("ldmatrix.sync.aligned.m8n8.x4.shared.b16 {%0,%1,%2,%3}, [%4];"
        : "=r"(r[0]), "=r"(r[1]), "=r"(r[2]), "=r"(r[3]) : "r"(addr));
}
__device__ __forceinline__ void ldm_x2(uint32_t* r, uint32_t addr) {
    asm volatile("ldmatrix.sync.aligned.m8n8.x2.shared.b16 {%0,%1}, [%2];"
        : "=r"(r[0]), "=r"(r[1]) : "r"(addr));
}

// A: single fp16 (rounded); 8-byte store
__device__ __forceinline__ void cvt_store_a(float4 v, uint16_t* hb, int idx) {
    __half h0 = __float2half_rn(v.x), h1 = __float2half_rn(v.y);
    __half h2 = __float2half_rn(v.z), h3 = __float2half_rn(v.w);
    uint32_t p0 = ((uint32_t)__half_as_ushort(h1) << 16) | __half_as_ushort(h0);
    uint32_t p1 = ((uint32_t)__half_as_ushort(h3) << 16) | __half_as_ushort(h2);
    *(uint2*)(hb + idx) = make_uint2(p0, p1);
}
// B: fp16 hi/lo split
__device__ __forceinline__ void cvt_store_b(float4 v, uint16_t* hb, uint16_t* lb, int idx) {
    __half h0 = __float2half_rn(v.x), h1 = __float2half_rn(v.y);
    __half h2 = __float2half_rn(v.z), h3 = __float2half_rn(v.w);
    uint32_t p0 = ((uint32_t)__half_as_ushort(h1) << 16) | __half_as_ushort(h0);
    uint32_t p1 = ((uint32_t)__half_as_ushort(h3) << 16) | __half_as_ushort(h2);
    *(uint2*)(hb + idx) = make_uint2(p0, p1);
    __half l0 = __float2half_rn(v.x - __half2float(h0));
    __half l1 = __float2half_rn(v.y - __half2float(h1));
    __half l2 = __float2half_rn(v.z - __half2float(h2));
    __half l3 = __float2half_rn(v.w - __half2float(h3));
    uint32_t q0 = ((uint32_t)__half_as_ushort(l1) << 16) | __half_as_ushort(l0);
    uint32_t q1 = ((uint32_t)__half_as_ushort(l3) << 16) | __half_as_ushort(l2);
    *(uint2*)(lb + idx) = make_uint2(q0, q1);
}

#define ASTR 40     // fp16 elems per smem row (32 data + 8 pad; conflict-free ldmatrix)

// ---- shared GEMM mainloop body: acc += A_f16 @ (Bh+Bl)^T  (2 MMAs/tile) ----
#define GEMM_MAINLOOP_STEP()                                                     \
    _Pragma("unroll")                                                            \
    for (int ks = 0; ks < 2; ks++) {                                             \
        const uint32_t kso = (uint32_t)(ks * 16) * 2;                            \
        uint32_t bh[4][2], bl[4][2];                                             \
        _Pragma("unroll")                                                        \
        for (int nt = 0; nt < 4; nt++) {                                         \
            uint32_t ad = boff + kso + (uint32_t)(nt * 8 * ASTR) * 2;            \
            ldm_x2(bh[nt], bbh + ad);                                            \
            ldm_x2(bl[nt], bbl + ad);                                            \
        }                                                                        \
        _Pragma("unroll")                                                        \
        for (int mt = 0; mt < 4; mt++) {                                         \
            uint32_t ad = aoff + kso + (uint32_t)(mt * 16 * ASTR) * 2;           \
            uint32_t ah[4];                                                      \
            ldm_x4(ah, abh + ad);                                                \
            _Pragma("unroll")                                                    \
            for (int nt = 0; nt < 4; nt++) {                                     \
                mma_f16(acc[mt][nt], ah, bh[nt]);                                \
                mma_f16(acc[mt][nt], ah, bl[nt]);                                \
            }                                                                    \
        }                                                                        \
    }

// ============ fp16x2 TN GEMM: C = A[M,K] @ W[N,K]^T (+bias/epi) ============
// grid (M/128, N/128), 256 thr. epi: 0 none, 1 relu, 2 +res
__global__ __launch_bounds__(256, 2) void tgemm(
    int M, int N, int K,
    const float* __restrict__ A, int lda,
    const float* __restrict__ W, int ldw,
    const float* __restrict__ bias,
    float* __restrict__ C, int ldc,
    int epi, const float* __restrict__ res, int ldres)
{
    __shared__ uint16_t Ah[128*ASTR], Bh[128*ASTR], Bl[128*ASTR];
    const int tid = threadIdx.x, lane = tid & 31, wid = tid >> 5;
    const int wm = wid >> 2, wn = wid & 3;
    const int bm = blockIdx.x * 128, bn = blockIdx.y * 128;

    float acc[4][4][4];
    #pragma unroll
    for (int i = 0; i < 4; i++)
        #pragma unroll
        for (int j = 0; j < 4; j++)
            #pragma unroll
            for (int l = 0; l < 4; l++) acc[i][j][l] = 0.f;

    const uint32_t abh = smem_u32(Ah);
    const uint32_t bbh = smem_u32(Bh), bbl = smem_u32(Bl);
    const int m_off = wm*64 + (lane & 7) + ((lane >> 3) & 1) * 8;
    const int ka    = (lane >> 4) * 8;
    const uint32_t aoff = (uint32_t)(m_off * ASTR + ka) * 2;
    const int n_off = wn*32 + (lane & 7);
    const int kb    = ((lane >> 3) & 1) * 8;
    const uint32_t boff = (uint32_t)(n_off * ASTR + kb) * 2;

    const int nkt = K >> 5;
    for (int kt = 0; kt < nkt; kt++) {
        const int k0 = kt << 5;
        #pragma unroll
        for (int l = 0; l < 4; l++) {
            int j = tid + l*256;
            int row = j >> 3, c4 = (j & 7) << 2;
            float4 va = *(const float4*)(A + (size_t)(bm + row)*lda + k0 + c4);
            cvt_store_a(va, Ah, row*ASTR + c4);
            float4 vb = *(const float4*)(W + (size_t)(bn + row)*ldw + k0 + c4);
            cvt_store_b(vb, Bh, Bl, row*ASTR + c4);
        }
        __syncthreads();
        GEMM_MAINLOOP_STEP();
        __syncthreads();
    }
    #pragma unroll
    for (int mt = 0; mt < 4; mt++) {
        int rlo = bm + wm*64 + mt*16 + (lane >> 2);
        #pragma unroll
        for (int nt = 0; nt < 4; nt++) {
            int col = bn + wn*32 + nt*8 + ((lane & 3) << 1);
            #pragma unroll
            for (int hf = 0; hf < 2; hf++) {
                int row = rlo + hf*8;
                float2 v = make_float2(acc[mt][nt][hf*2], acc[mt][nt][hf*2+1]);
                if (bias) { v.x += bias[col]; v.y += bias[col+1]; }
                if (epi == 1) { v.x = fmaxf(v.x, 0.f); v.y = fmaxf(v.y, 0.f); }
                else if (epi == 2) {
                    float2 rv = *(const float2*)(res + (size_t)row*ldres + col);
                    v.x += rv.x; v.y += rv.y;
                }
                *(float2*)(C + (size_t)row*ldc + col) = v;
            }
        }
    }
}

// ============ neighbor logits: gathered fp16 GEMM + tanh/dot epilogue ============
__global__ __launch_bounds__(256, 2) void neigh_tc(
    const float* __restrict__ emb, const float* __restrict__ embv,
    const float* __restrict__ nW,  const float* __restrict__ nWb,
    const float* __restrict__ nu,  const float* __restrict__ nub,
    const float* __restrict__ nvW, const float* __restrict__ nvWb,
    const float* __restrict__ nvu, const float* __restrict__ nvub,
    const int* __restrict__ ql, const int* __restrict__ qr,
    const int* __restrict__ sl, const int* __restrict__ sr)
{
    __shared__ uint16_t Ah[128*ASTR], Bh[128*ASTR], Bl[128*ASTR];
    __shared__ int relS[128], entS[128];
    __shared__ float sU[128], sB[128];
    __shared__ float sred[4][128];

    const int path = blockIdx.y;
    const float* tab = path ? embv : emb;
    const float* Wt  = path ? nvW  : nW;
    const float* Wb  = path ? nvWb : nWb;
    const float* uu  = path ? nvu  : nu;
    const float  ub  = path ? nvub[0] : nub[0];

    const int tid = threadIdx.x, lane = tid & 31, wid = tid >> 5;
    const int wm = wid >> 2, wn = wid & 3;
    const int bm = blockIdx.x * 128;

    if (tid < 128) {
        int r = bm + tid;
        int rel = 0, ent = 0;
        if (r < R_TOT) {
            const int* conn; int local;
            if (r < RQ)            { conn = ql; local = r; }
            else if (r < 2*RQ)     { conn = qr; local = r - RQ; }
            else if (r < 2*RQ+RS)  { conn = sl; local = r - 2*RQ; }
            else                   { conn = sr; local = r - 2*RQ - RS; }
            rel = conn[local*2]; ent = conn[local*2+1];
        }
        relS[tid] = rel; entS[tid] = ent;
        sU[tid] = uu[tid]; sB[tid] = Wb[tid];
    }
    __syncthreads();

    float acc[4][4][4];
    #pragma unroll
    for (int i = 0; i < 4; i++)
        #pragma unroll
        for (int j = 0; j < 4; j++)
            #pragma unroll
            for (int l = 0; l < 4; l++) acc[i][j][l] = 0.f;

    const uint32_t abh = smem_u32(Ah);
    const uint32_t bbh = smem_u32(Bh), bbl = smem_u32(Bl);
    const int m_off = wm*64 + (lane & 7) + ((lane >> 3) & 1) * 8;
    const int ka    = (lane >> 4) * 8;
    const uint32_t aoff = (uint32_t)(m_off * ASTR + ka) * 2;
    const int n_off = wn*32 + (lane & 7);
    const int kb    = ((lane >> 3) & 1) * 8;
    const uint32_t boff = (uint32_t)(n_off * ASTR + kb) * 2;

    for (int kt = 0; kt < 8; kt++) {               // K = 256
        const int half = kt >> 2;
        const int koff = (kt & 3) << 5;
        #pragma unroll
        for (int l = 0; l < 4; l++) {
            int j = tid + l*256;
            int row = j >> 3, c4 = (j & 7) << 2;
            int sym = half ? entS[row] : relS[row];
            float4 va = *(const float4*)(tab + (size_t)sym*DD + koff + c4);
            cvt_store_a(va, Ah, row*ASTR + c4);
            float4 vb = *(const float4*)(Wt + (size_t)row*(2*DD) + (kt << 5) + c4);
            cvt_store_b(vb, Bh, Bl, row*ASTR + c4);
        }
        __syncthreads();
        GEMM_MAINLOOP_STEP();
        __syncthreads();
    }
    // epilogue: logit = ub + sum_col u[col]*tanh(acc + b[col])
    #pragma unroll
    for (int mt = 0; mt < 4; mt++) {
        float pLo = 0.f, pHi = 0.f;
        #pragma unroll
        for (int nt = 0; nt < 4; nt++) {
            int c0 = wn*32 + nt*8 + ((lane & 3) << 1);
            pLo += sU[c0]   * tanhf(acc[mt][nt][0] + sB[c0]);
            pLo += sU[c0+1] * tanhf(acc[mt][nt][1] + sB[c0+1]);
            pHi += sU[c0]   * tanhf(acc[mt][nt][2] + sB[c0]);
            pHi += sU[c0+1] * tanhf(acc[mt][nt][3] + sB[c0+1]);
        }
        pLo += __shfl_xor_sync(~0u, pLo, 1); pLo += __shfl_xor_sync(~0u, pLo, 2);
        pHi += __shfl_xor_sync(~0u, pHi, 1); pHi += __shfl_xor_sync(~0u, pHi, 2);
        if ((lane & 3) == 0) {
            int rl = wm*64 + mt*16 + (lane >> 2);
            sred[wn][rl]   = pLo;
            sred[wn][rl+8] = pHi;
        }
    }
    __syncthreads();
    if (tid < 128) {
        int row = bm + tid;
        if (row < R_TOT) {
            float s = sred[0][tid] + sred[1][tid] + sred[2][tid] + sred[3][tid];
            g_logits[(size_t)path*R_TOT + row] = s + ub;
        }
    }
}

// ---------------- small GEMM (warp per output) ----------------------------------
__global__ __launch_bounds__(256) void small_gemm(
    int M, int N, int K,
    const float* __restrict__ A, int lda,
    const float* __restrict__ W, int ldw,
    const float* __restrict__ bias,
    float* __restrict__ C, int ldc,
    int epi, const float* __restrict__ res, int ldres)
{
    int w = (blockIdx.x * 256 + threadIdx.x) >> 5;
    int lane = threadIdx.x & 31;
    if (w >= M * N) return;
    int m = w / N, n = w % N;
    float p = 0.f;
    for (int k = lane; k < K; k += 32) p += A[(size_t)m*lda + k] * W[(size_t)n*ldw + k];
    #pragma unroll
    for (int o = 16; o; o >>= 1) p += __shfl_xor_sync(~0u, p, o);
    if (lane == 0) {
        if (bias) p += bias[n];
        if (epi == 1) p = fmaxf(p, 0.f);
        else if (epi == 2) p += res[(size_t)m*ldres + n];
        C[(size_t)m*ldc + n] = p;
    }
}

// ---------------- softmax over 30 neighbors + weighted pool + tanh --------------
__global__ __launch_bounds__(128) void pool_kernel(
    const float* __restrict__ emb,
    const int* __restrict__ ql, const int* __restrict__ qr,
    const int* __restrict__ sl, const int* __restrict__ sr)
{
    const int gs = blockIdx.x;
    const int tid = threadIdx.x;
    __shared__ float att[2][NBR];
    __shared__ int entS[NBR];
    int set, local;
    if (gs < NQ)            { set=0; local=gs; }
    else if (gs < 2*NQ)     { set=1; local=gs-NQ; }
    else if (gs < 2*NQ+FEWN){ set=2; local=gs-2*NQ; }
    else                    { set=3; local=gs-2*NQ-FEWN; }
    const int rowbase = (set==0?0: set==1?RQ : set==2?2*RQ : 2*RQ+RS) + local*NBR;
    const int* conn = set==0?ql : set==1?qr : set==2?sl : sr;
    const int warp = tid >> 5, lane = tid & 31;

    if (warp == 0 && lane < NBR) entS[lane] = conn[(local*NBR+lane)*2+1];
    if (warp < 2) {
        float v = (lane < NBR) ? g_logits[(size_t)warp*R_TOT + rowbase + lane] : -1e30f;
        float m = v;
        #pragma unroll
        for (int o = 16; o; o >>= 1) m = fmaxf(m, __shfl_xor_sync(~0u, m, o));
        float e = (lane < NBR) ? expf(v - m) : 0.f;
        float s = e;
        #pragma unroll
        for (int o = 16; o; o >>= 1) s += __shfl_xor_sync(~0u, s, o);
        if (lane < NBR) att[warp][lane] = e / s;
    }
    __syncthreads();
    const int d = tid;
    float a0 = 0.f, a1 = 0.f;
    #pragma unroll 6
    for (int nb = 0; nb < NBR; nb++) {
        float ev = emb[(size_t)entS[nb]*DD + d];
        a0 += att[0][nb]*ev;
        a1 += att[1][nb]*ev;
    }
    float t0 = tanhf(a0), t1 = tanhf(a1);
    if (set < 2) {
        g_query[((size_t)0*NQ + local)*H2 + set*DD + d] = t0;
        g_query[((size_t)NQ + local)*H2 + set*DD + d]   = t1;
    } else {
        int s2 = set - 2;
        g_support[(0*FEWN + local)*H2 + s2*DD + d] = t0;
        g_support[(1*FEWN + local)*H2 + s2*DD + d] = t1;
    }
}

// ---------------- layernorm (ddof=1, eps added to sigma) ------------------------
__global__ __launch_bounds__(256) void ln_kernel(
    const float* __restrict__ Z, float* __restrict__ O,
    const float* __restrict__ ga, const float* __restrict__ gb)
{
    const int row = blockIdx.x, c = threadIdx.x;
    float z = Z[(size_t)row*H2 + c];
    __shared__ float s1[H2], s2[H2];
    s1[c] = z; s2[c] = z*z;
    __syncthreads();
    for (int o = 128; o; o >>= 1) {
        if (c < o) { s1[c] += s1[c+o]; s2[c] += s2[c+o]; }
        __syncthreads();
    }
    float mu  = s1[0] * (1.f/H2);
    float var = (s2[0] - (float)H2*mu*mu) * (1.f/(H2-1));
    float sig = sqrtf(fmaxf(var, 0.f));
    O[(size_t)row*H2 + c] = (z - mu)/(sig + 1e-3f)*ga[c] + gb[c];
}

__global__ void smean_kernel() {
    int p = blockIdx.x, c = threadIdx.x;
    float s = 0.f;
    #pragma unroll
    for (int f = 0; f < FEWN; f++) s += g_sg[(p*FEWN + f)*H2 + c];
    g_smean[p*H2 + c] = s * (1.f/FEWN);
}

__global__ void bsum_kernel(const float* __restrict__ bih, const float* __restrict__ bhh) {
    int i = blockIdx.x*blockDim.x + threadIdx.x;
    if (i < NG) g_bsum[i] = bih[i] + bhh[i];
}

// ---------------- LSTM elementwise step (+ rank-5 attn@SW fold) -----------------
__global__ __launch_bounds__(256) void lstm_ew_kernel(int t)
{
    int idx = blockIdx.x*256 + threadIdx.x;
    int r = idx >> 9, u = idx & 511;
    const float* G = (t > 0) ? g_Ds : g_Gx;
    size_t base = (size_t)r*NG;
    float gi = G[base+u],      gf = G[base+512+u];
    float gg = G[base+1024+u], go = G[base+1536+u];
    float cprev = 0.f;
    if (t > 0) {
        const float* SW = g_SW + (size_t)(r >> 12) * FEWN * NG;
        #pragma unroll
        for (int f = 0; f < FEWN; f++) {
            float a = g_attn[r*FEWN + f];
            gi += a*SW[f*NG + u];
            gf += a*SW[f*NG + 512 + u];
            gg += a*SW[f*NG + 1024 + u];
            go += a*SW[f*NG + 1536 + u];
        }
        cprev = g_c[(size_t)r*H4 + u];
    }
    float cn = sigm(gf)*cprev + sigm(gi)*tanhf(gg);
    g_c[(size_t)r*H4 + u] = cn;
    if (u < H2) {
        float ho = sigm(go)*tanhf(cn);
        g_h[(size_t)r*H2 + u] = g_qg[(size_t)r*H2 + u] + ho;
    }
}

// ---------------- attention over 5 support rows ---------------------------------
__global__ __launch_bounds__(128) void attn_kernel()
{
    int r = blockIdx.x*4 + (threadIdx.x >> 5);
    int lane = threadIdx.x & 31;
    const float* sg = g_sg + (size_t)(r >> 12) * FEWN * H2;
    float sc[FEWN];
    #pragma unroll
    for (int f = 0; f < FEWN; f++) {
        float p = 0.f;
        for (int c = lane; c < H2; c += 32) p += g_h[(size_t)r*H2 + c]*sg[f*H2 + c];
        #pragma unroll
        for (int o = 16; o; o >>= 1) p += __shfl_xor_sync(~0u, p, o);
        sc[f] = p;
    }
    float m = sc[0];
    #pragma unroll
    for (int f = 1; f < FEWN; f++) m = fmaxf(m, sc[f]);
    float e[FEWN], s = 0.f;
    #pragma unroll
    for (int f = 0; f < FEWN; f++) { e[f] = expf(sc[f]-m); s += e[f]; }
    if (lane < FEWN) g_attn[r*FEWN + lane] = e[lane]/s;
}

__global__ __launch_bounds__(128) void score_kernel(float* __restrict__ out)
{
    int r = blockIdx.x*4 + (threadIdx.x >> 5);
    int lane = threadIdx.x & 31;
    const float* sm = g_smean + (size_t)(r >> 12) * H2;
    float p = 0.f;
    for (int c = lane; c < H2; c += 32) p += g_h[(size_t)r*H2 + c]*sm[c];
    #pragma unroll
    for (int o = 16; o; o >>= 1) p += __shfl_xor_sync(~0u, p, o);
    if (lane == 0) out[r] = p;
}

// ---------------- host orchestration --------------------------------------------
extern "C" void kernel_launch(void* const* d_in, const int* in_sizes, int n_in,
                              void* d_out, int out_size)
{
    (void)in_sizes; (void)n_in; (void)out_size;
    const float* emb   = (const float*)d_in[0];
    const float* embv  = (const float*)d_in[1];
    const float* nW    = (const float*)d_in[2];
    const float* nWb   = (const float*)d_in[3];
    const float* nu    = (const float*)d_in[4];
    const float* nub   = (const float*)d_in[5];
    const float* nvW   = (const float*)d_in[6];
    const float* nvWb  = (const float*)d_in[7];
    const float* nvu   = (const float*)d_in[8];
    const float* nvub  = (const float*)d_in[9];
    const float* p1W   = (const float*)d_in[10];
    const float* p1b   = (const float*)d_in[11];
    const float* p2W   = (const float*)d_in[12];
    const float* p2b   = (const float*)d_in[13];
    const float* ln_a  = (const float*)d_in[14];
    const float* ln_b  = (const float*)d_in[15];
    const float* Wih   = (const float*)d_in[16];
    const float* Whh   = (const float*)d_in[17];
    const float* bih   = (const float*)d_in[18];
    const float* bhh   = (const float*)d_in[19];
    const int* ql = (const int*)d_in[20];
    const int* qr = (const int*)d_in[21];
    const int* sl = (const int*)d_in[22];
    const int* sr = (const int*)d_in[23];
    float* out = (float*)d_out;

    float *p_query, *p_support, *p_qg, *p_sg, *p_h1, *p_z, *p_sh1, *p_sz,
          *p_Gx, *p_Ds, *p_SW, *p_h, *p_bsum;
    cudaGetSymbolAddress((void**)&p_query,   g_query);
    cudaGetSymbolAddress((void**)&p_support, g_support);
    cudaGetSymbolAddress((void**)&p_qg,      g_qg);
    cudaGetSymbolAddress((void**)&p_sg,      g_sg);
    cudaGetSymbolAddress((void**)&p_h1,      g_h1);
    cudaGetSymbolAddress((void**)&p_z,       g_z);
    cudaGetSymbolAddress((void**)&p_sh1,     g_sh1);
    cudaGetSymbolAddress((void**)&p_sz,      g_sz);
    cudaGetSymbolAddress((void**)&p_Gx,      g_Gx);
    cudaGetSymbolAddress((void**)&p_Ds,      g_Ds);
    cudaGetSymbolAddress((void**)&p_SW,      g_SW);
    cudaGetSymbolAddress((void**)&p_h,       g_h);
    cudaGetSymbolAddress((void**)&p_bsum,    g_bsum);

    bsum_kernel<<<(NG+255)/256, 256>>>(bih, bhh);

    dim3 gN((R_TOT + 127)/128, 2);
    neigh_tc<<<gN, 256>>>(emb, embv, nW, nWb, nu, nub,
                          nvW, nvWb, nvu, nvub, ql, qr, sl, sr);
    pool_kernel<<<2*NQ + 2*FEWN, 128>>>(emb, ql, qr, sl, sr);

    // ---- support rows (M=10, both paths) ----
    {
        int M = 2*FEWN;
        small_gemm<<<(M*H4*32 + 255)/256, 256>>>(M, H4, H2, p_support, H2, p1W, H2,
                                                 p1b, p_sh1, H4, 1, nullptr, 0);
        small_gemm<<<(M*H2*32 + 255)/256, 256>>>(M, H2, H4, p_sh1, H4, p2W, H4,
                                                 p2b, p_sz, H2, 2, p_support, H2);
        ln_kernel<<<M, 256>>>(p_sz, p_sg, ln_a, ln_b);
        small_gemm<<<(M*NG*32 + 255)/256, 256>>>(M, NG, H2, p_sg, H2, Whh + 256, H4,
                                                 nullptr, p_SW, NG, 0, nullptr, 0);
        smean_kernel<<<2, 256>>>();
    }

    // ---- support encoder on queries (M=8192) ----
    tgemm<<<dim3(MB/128, H4/128), 256>>>(MB, H4, H2, p_query, H2, p1W, H2,
                                         p1b, p_h1, H4, 1, nullptr, 0);
    tgemm<<<dim3(MB/128, H2/128), 256>>>(MB, H2, H4, p_h1, H4, p2W, H4,
                                         p2b, p_z, H2, 2, p_query, H2);
    ln_kernel<<<MB, 256>>>(p_z, p_qg, ln_a, ln_b);

    // ---- G_x = q_g @ Wih^T + (bih+bhh) ----
    tgemm<<<dim3(MB/128, NG/128), 256>>>(MB, NG, H2, p_qg, H2, Wih, H2,
                                         p_bsum, p_Gx, NG, 0, nullptr, 0);

    // ---- LSTM steps ----
    lstm_ew_kernel<<<MB*H4/256, 256>>>(0);
    attn_kernel<<<MB/4, 128>>>();
    for (int t = 1; t < 4; t++) {
        // Ds = h @ WhhA^T + Gx  (residual fused)
        tgemm<<<dim3(MB/128, NG/128), 256>>>(MB, NG, H2, p_h, H2, Whh, H4,
                                             nullptr, p_Ds, NG, 2, p_Gx, NG);
        lstm_ew_kernel<<<MB*H4/256, 256>>>(t);
        if (t < 3) attn_kernel<<<MB/4, 128>>>();
    }
    score_kernel<<<MB/4, 128>>>(out);
}